// round 3
// baseline (speedup 1.0000x reference)
#include <cuda_runtime.h>

// GooLayer: B=2, M=64, D=64, T=8192
// Per-lane chain (lane = d), per warp-unit = (bm, D-half):
//   g_t  = f_t + ki*h_t                     (state-independent, batched at load)
//   acc  = g_t - ki*pos_{t-1}
//   vs_t = vs_{t-1}*DAMP + acc
//   pos  = pos + vs_t*DAMP
//   out contribution: tanh(vs_t*DAMP*gain)*mic, reduced over d.
// tanh via ex2+rcp: tanh(x) = 1 - 2/(2^(2x*log2e) + 1)
//
// Software pipeline per 32-step window w:
//   [prefetch loads w+1] | [TANH batch of window w-1] | [RECUR chain window w]
//   syncwarp ; [transpose-REDUCE window w-1] ; syncwarp ; [g-convert w+1]

#define BB 2
#define MM 64
#define DD 64
#define TT 8192
#define DAMP 0.9998f
#define WIN 32
#define NW (TT / WIN)   // 256 windows
#define NV (WIN / 4)    // 8 float4 per window
#define TSTRIDE 36      // tile row stride in floats (144B: 16B-aligned, conflict-free)

__device__ float4 g_partial[2][(BB * MM * TT) / 4];

__device__ __forceinline__ float ex2_fast(float x) {
    float y; asm("ex2.approx.f32 %0, %1;" : "=f"(y) : "f"(x)); return y;
}
__device__ __forceinline__ float rcp_fast(float x) {
    float y; asm("rcp.approx.f32 %0, %1;" : "=f"(y) : "f"(x)); return y;
}

__global__ __launch_bounds__(64, 1)
void goo_scan_kernel(const float* __restrict__ forces,
                     const float* __restrict__ home,
                     const float* __restrict__ mic,
                     const float* __restrict__ masses,
                     const float* __restrict__ tensions,
                     const float* __restrict__ gains)
{
    // One warp per (bm, D-half). 128 blocks x 2 warps = 256 warp-units.
    __shared__ float sh[2][WIN][TSTRIDE];

    const int tid  = threadIdx.x;
    const int wid  = tid >> 5;
    const int lane = tid & 31;
    const int u    = blockIdx.x * 2 + wid;   // 0..255
    const int bm   = u >> 1;                 // 0..127
    const int half = u & 1;
    const int m    = bm & (MM - 1);
    const int d    = half * 32 + lane;

    const float ki    = tensions[m * DD + d] / masses[m];
    const float nki   = -ki;
    const float karg  = gains[m] * (DAMP * 2.0f * 1.4426950408889634f);
    const float micv  = mic[bm * DD + d];
    const float m2mic = -2.0f * micv;

    const size_t base = ((size_t)bm * DD + d) * TT;
    const float4* __restrict__ f4p = (const float4*)(forces + base);
    const float4* __restrict__ h4p = (const float4*)(home + base);

    float* rpart = (float*)g_partial[half] + (size_t)bm * TT;
    float (*tile)[TSTRIDE] = sh[wid];

    float pos = 0.0f, vs = 0.0f;

    // a-value double buffer (compile-time parity via macro expansion)
    float aA[WIN], aB[WIN];
    float gb[WIN];

    // Prologue: load + convert window 0
    {
        #pragma unroll
        for (int i = 0; i < NV; i++) {
            float4 fv = __ldcs(f4p + i);
            float4 hv = __ldcs(h4p + i);
            #pragma unroll
            for (int j = 0; j < 4; j++)
                gb[4 * i + j] = fmaf(ki, (&hv.x)[j], (&fv.x)[j]);
        }
    }

    // Body for one window. APREV/ACUR are register arrays selected at compile time.
#define GOO_BODY(W, APREV, ACUR)                                               \
    {                                                                          \
        const int w_ = (W);                                                    \
        float4 rf[NV], rh[NV];                                                 \
        const bool more_ = (w_ + 1 < NW);                                      \
        if (more_) {                                                           \
            const int o_ = (w_ + 1) * NV;                                      \
            _Pragma("unroll")                                                  \
            for (int i = 0; i < NV; i++) {                                     \
                rf[i] = __ldcs(f4p + o_ + i);                                  \
                rh[i] = __ldcs(h4p + o_ + i);                                  \
            }                                                                  \
        }                                                                      \
        /* TANH batch: previous window (independent chains) */                 \
        if (w_ > 0) {                                                          \
            _Pragma("unroll")                                                  \
            for (int j = 0; j < WIN; j++) {                                    \
                float e = ex2_fast(APREV[j]);                                  \
                float r = rcp_fast(e + 1.0f);                                  \
                tile[j][lane] = fmaf(r, m2mic, micv);                          \
            }                                                                  \
        }                                                                      \
        /* RECUR: serial 3-FMA chain for current window */                     \
        _Pragma("unroll")                                                      \
        for (int j = 0; j < WIN; j++) {                                        \
            float acc = fmaf(nki, pos, gb[j]);                                 \
            vs  = fmaf(vs, DAMP, acc);                                         \
            pos = fmaf(vs, DAMP, pos);                                         \
            ACUR[j] = vs * karg;                                               \
        }                                                                      \
        if (w_ > 0) {                                                          \
            __syncwarp();                                                      \
            /* transpose-reduce window w_-1: lane sums its row over 32 d */    \
            float s0 = 0.f, s1 = 0.f, s2 = 0.f, s3 = 0.f;                      \
            _Pragma("unroll")                                                  \
            for (int i = 0; i < 8; i++) {                                      \
                float4 v = *(const float4*)&tile[lane][4 * i];                 \
                s0 += v.x; s1 += v.y; s2 += v.z; s3 += v.w;                    \
            }                                                                  \
            rpart[(w_ - 1) * WIN + lane] = (s0 + s1) + (s2 + s3);              \
            __syncwarp();                                                      \
        }                                                                      \
        /* convert prefetched raw -> g for window w_+1 */                      \
        if (more_) {                                                           \
            _Pragma("unroll")                                                  \
            for (int i = 0; i < NV; i++) {                                     \
                _Pragma("unroll")                                              \
                for (int j = 0; j < 4; j++)                                    \
                    gb[4 * i + j] = fmaf(ki, (&rh[i].x)[j], (&rf[i].x)[j]);    \
            }                                                                  \
        }                                                                      \
    }

    for (int w = 0; w < NW; w += 2) {
        GOO_BODY(w,     aB, aA)   // even w: produces aA, consumes aB (w-1 odd)
        GOO_BODY(w + 1, aA, aB)   // odd  w: produces aB, consumes aA
    }

    // Epilogue: TANH + REDUCE for the last window (NW-1 = 255, odd -> aB)
    {
        #pragma unroll
        for (int j = 0; j < WIN; j++) {
            float e = ex2_fast(aB[j]);
            float r = rcp_fast(e + 1.0f);
            tile[j][lane] = fmaf(r, m2mic, micv);
        }
        __syncwarp();
        float s0 = 0.f, s1 = 0.f, s2 = 0.f, s3 = 0.f;
        #pragma unroll
        for (int i = 0; i < 8; i++) {
            float4 v = *(const float4*)&tile[lane][4 * i];
            s0 += v.x; s1 += v.y; s2 += v.z; s3 += v.w;
        }
        rpart[(NW - 1) * WIN + lane] = (s0 + s1) + (s2 + s3);
    }
#undef GOO_BODY
}

// Sum the two D-half partials into d_out.
__global__ __launch_bounds__(512, 2)
void goo_combine_kernel(float4* __restrict__ out)
{
    int i = blockIdx.x * blockDim.x + threadIdx.x;  // 0 .. 262143
    float4 a = g_partial[0][i];
    float4 b = g_partial[1][i];
    out[i] = make_float4(a.x + b.x, a.y + b.y, a.z + b.z, a.w + b.w);
}

extern "C" void kernel_launch(void* const* d_in, const int* in_sizes, int n_in,
                              void* d_out, int out_size)
{
    const float* forces   = (const float*)d_in[0];
    const float* home     = (const float*)d_in[1];
    const float* mic      = (const float*)d_in[2];
    const float* masses   = (const float*)d_in[3];
    const float* tensions = (const float*)d_in[4];
    const float* gains    = (const float*)d_in[5];

    goo_scan_kernel<<<128, 64>>>(forces, home, mic, masses, tensions, gains);
    goo_combine_kernel<<<512, 512>>>((float4*)d_out);
}